// round 14
// baseline (speedup 1.0000x reference)
#include <cuda_runtime.h>
#include <cuda_bf16.h>
#include <math.h>
#include <math_constants.h>
#include <cstdint>

#define BB 4
#define SS 2048
#define EE 1024
#define HH 16
#define DD 64
#define MROWS (BB*SS)          // 8192

// -------- device scratch (statically allocated; no cudaMalloc allowed) -----
__device__ __nv_bfloat16 g_xqh[8388608], g_xql[8388608];
__device__ __nv_bfloat16 g_xkh[8388608], g_xkl[8388608];
__device__ __nv_bfloat16 g_xvh[8388608], g_xvl[8388608];
__device__ __nv_bfloat16 g_wh[3145728],  g_wl[3145728];    // in_proj W [3E,E]
__device__ __nv_bfloat16 g_woh[1048576], g_wol[1048576];   // out_proj W [E,E]
__device__ __nv_bfloat16 g_qh[8388608],  g_ql[8388608];
__device__ __nv_bfloat16 g_kh[8388608],  g_kl[8388608];
__device__ __nv_bfloat16 g_vh[8388608],  g_vl[8388608];
__device__ __nv_bfloat16 g_vth[8388608], g_vtl[8388608];   // V^T [B,H,D,S]
__device__ __nv_bfloat16 g_ah[8388608],  g_al[8388608];    // att split
__device__ float g_invz[131072];                           // 1/Z per (b,h,q)

// ============================ PTX helpers ==================================
__device__ __forceinline__ uint32_t smem_u32(const void* p) {
    uint32_t a;
    asm("{ .reg .u64 t; cvta.to.shared.u64 t, %1; cvt.u32.u64 %0, t; }"
        : "=r"(a) : "l"(p));
    return a;
}
__device__ __forceinline__ void ldsm_x4(uint32_t* r, uint32_t addr) {
    asm volatile("ldmatrix.sync.aligned.m8n8.x4.shared.b16 {%0,%1,%2,%3}, [%4];"
        : "=r"(r[0]), "=r"(r[1]), "=r"(r[2]), "=r"(r[3]) : "r"(addr));
}
__device__ __forceinline__ void mma_bf16(float* d, const uint32_t* a, const uint32_t* b) {
    asm volatile("mma.sync.aligned.m16n8k16.row.col.f32.bf16.bf16.f32 "
        "{%0,%1,%2,%3}, {%4,%5,%6,%7}, {%8,%9}, {%0,%1,%2,%3};"
        : "+f"(d[0]), "+f"(d[1]), "+f"(d[2]), "+f"(d[3])
        : "r"(a[0]), "r"(a[1]), "r"(a[2]), "r"(a[3]), "r"(b[0]), "r"(b[1]));
}
__device__ __forceinline__ void split2(float v, __nv_bfloat16& h, __nv_bfloat16& l) {
    h = __float2bfloat16_rn(v);
    l = __float2bfloat16_rn(v - __bfloat162float(h));
}
__device__ __forceinline__ uint32_t packbf(__nv_bfloat16 a, __nv_bfloat16 b) {
    return (uint32_t)__bfloat16_as_ushort(a) | ((uint32_t)__bfloat16_as_ushort(b) << 16);
}
#define CP16(dst, src) \
    asm volatile("cp.async.cg.shared.global [%0], [%1], 16;" :: "r"(dst), "l"(src))
#define CP_COMMIT() asm volatile("cp.async.commit_group;" ::: "memory")
#define CP_WAIT1()  asm volatile("cp.async.wait_group 1;" ::: "memory")
#define CP_WAIT0()  asm volatile("cp.async.wait_group 0;" ::: "memory")

#define LDA 40   // smem row stride in halves for 32-wide chunks

// ============================ split kernel =================================
__global__ void __launch_bounds__(256)
split_kernel(const float* __restrict__ src,
             __nv_bfloat16* __restrict__ hi,
             __nv_bfloat16* __restrict__ lo, int n4)
{
    int i = blockIdx.x * 256 + threadIdx.x;
    if (i >= n4) return;
    float4 x = ((const float4*)src)[i];
    __nv_bfloat16 h0, h1, h2, h3, l0, l1, l2, l3;
    split2(x.x, h0, l0); split2(x.y, h1, l1);
    split2(x.z, h2, l2); split2(x.w, h3, l3);
    uint2 hv, lv;
    hv.x = packbf(h0, h1); hv.y = packbf(h2, h3);
    lv.x = packbf(l0, l1); lv.y = packbf(l2, l3);
    *(uint2*)(hi + (size_t)i * 4) = hv;
    *(uint2*)(lo + (size_t)i * 4) = lv;
}

// ============================ HMMA GEMM (projections) ======================
#define GPL  (128 * LDA * 2)     // 10240 B per plane
#define GSTG (4 * GPL)           // 40960 B per stage
#define GDSM (2 * GSTG)          // 81920 B

__global__ void __launch_bounds__(256)
gemm_split_kernel(const __nv_bfloat16* __restrict__ Ah_,
                  const __nv_bfloat16* __restrict__ Al_,
                  const __nv_bfloat16* __restrict__ Bh_,
                  const __nv_bfloat16* __restrict__ Bl_,
                  const float* __restrict__ bias,
                  float* __restrict__ dst32,
                  __nv_bfloat16* __restrict__ dsth,
                  __nv_bfloat16* __restrict__ dstl, int mode)
{
    extern __shared__ char dsm[];
    const uint32_t sb = smem_u32(dsm);
    const int tid = threadIdx.x;
    const int w = tid >> 5, lane = tid & 31;
    const int wm = w & 1, wn = w >> 1;
    const int row0 = blockIdx.y * 128, col0 = blockIdx.x * 128;

    float acc[4][4][4] = {};

    const int a_r = lane & 15;
    const int a_c = (lane >> 4) << 3;
    const int b_n = (lane & 7) + ((lane >> 4) & 1) * 8;
    const int b_k = ((lane >> 3) & 1) * 8;
    const int ld_r  = tid >> 2;
    const int ld_c8 = (tid & 3) << 3;

    auto prefetch = [&](int it, int stage) {
        const int k0 = it * 32;
        const uint32_t s0 = sb + stage * GSTG;
        #pragma unroll
        for (int u = 0; u < 2; u++) {
            const int r = ld_r + u * 64;
            const uint32_t off = (uint32_t)(r * LDA + ld_c8) * 2;
            const size_t ga = (size_t)(row0 + r) * EE + k0 + ld_c8;
            const size_t gb = (size_t)(col0 + r) * EE + k0 + ld_c8;
            CP16(s0 + off,           Ah_ + ga);
            CP16(s0 + GPL + off,     Al_ + ga);
            CP16(s0 + 2 * GPL + off, Bh_ + gb);
            CP16(s0 + 3 * GPL + off, Bl_ + gb);
        }
        CP_COMMIT();
    };

    prefetch(0, 0);
    for (int it = 0; it < 32; it++) {
        const int stage = it & 1;
        if (it + 1 < 32) { prefetch(it + 1, stage ^ 1); CP_WAIT1(); }
        else             { CP_WAIT0(); }
        __syncthreads();
        const uint32_t s0 = sb + stage * GSTG;
        #pragma unroll
        for (int ks = 0; ks < 32; ks += 16) {
            uint32_t bfh[4][2], bfl[4][2];
            #pragma unroll
            for (int pr = 0; pr < 2; pr++) {
                const int nrow = wn * 32 + pr * 16 + b_n;
                uint32_t t[4];
                ldsm_x4(t, s0 + 2 * GPL + (uint32_t)(nrow * LDA + ks + b_k) * 2);
                bfh[2*pr][0] = t[0]; bfh[2*pr][1] = t[1];
                bfh[2*pr+1][0] = t[2]; bfh[2*pr+1][1] = t[3];
                ldsm_x4(t, s0 + 3 * GPL + (uint32_t)(nrow * LDA + ks + b_k) * 2);
                bfl[2*pr][0] = t[0]; bfl[2*pr][1] = t[1];
                bfl[2*pr+1][0] = t[2]; bfl[2*pr+1][1] = t[3];
            }
            uint32_t af[4][4];
            #pragma unroll
            for (int mt = 0; mt < 4; mt++)
                ldsm_x4(af[mt], s0 + (uint32_t)((wm*64 + mt*16 + a_r) * LDA + ks + a_c) * 2);
            #pragma unroll
            for (int mt = 0; mt < 4; mt++)
                #pragma unroll
                for (int nt = 0; nt < 4; nt++) {
                    mma_bf16(acc[mt][nt], af[mt], bfh[nt]);
                    mma_bf16(acc[mt][nt], af[mt], bfl[nt]);
                }
            #pragma unroll
            for (int mt = 0; mt < 4; mt++)
                ldsm_x4(af[mt], s0 + GPL + (uint32_t)((wm*64 + mt*16 + a_r) * LDA + ks + a_c) * 2);
            #pragma unroll
            for (int mt = 0; mt < 4; mt++)
                #pragma unroll
                for (int nt = 0; nt < 4; nt++)
                    mma_bf16(acc[mt][nt], af[mt], bfh[nt]);
        }
        __syncthreads();
    }

    const int r4 = lane >> 2, c2 = (lane & 3) << 1;
    float bs0[4], bs1[4], invs[4];
    #pragma unroll
    for (int nt = 0; nt < 4; nt++) {
        const int col = col0 + wn * 32 + nt * 8 + c2;
        bs0[nt] = bias[col];
        bs1[nt] = bias[col + 1];
        invs[nt] = expf(-(float)((col & 63) >> 1) * 0.28782313662425567f);
    }

    #pragma unroll
    for (int mt = 0; mt < 4; mt++) {
        #pragma unroll
        for (int rh = 0; rh < 2; rh++) {
            const int m = row0 + wm * 64 + mt * 16 + rh * 8 + r4;
            const int b = m >> 11, s = m & 2047;
            #pragma unroll
            for (int nt = 0; nt < 4; nt++) {
                const int col = col0 + wn * 32 + nt * 8 + c2;
                float v0 = acc[mt][nt][rh * 2 + 0] + bs0[nt];
                float v1 = acc[mt][nt][rh * 2 + 1] + bs1[nt];
                if (mode == 0) {
                    *(float2*)(dst32 + (size_t)m * EE + col) = make_float2(v0, v1);
                } else {
                    if (mode == 2) {
                        float sn, cs;
                        sincosf((float)s * invs[nt], &sn, &cs);
                        const float t0 = v0, t1 = v1;
                        v0 = t0 * cs - t1 * sn;
                        v1 = t1 * cs + t0 * sn;
                    }
                    const int h = col >> 6, d0 = col & 63;
                    const size_t off = ((size_t)(b * HH + h) * SS + s) * DD + d0;
                    __nv_bfloat16 h0, h1, l0, l1;
                    split2(v0, h0, l0); split2(v1, h1, l1);
                    *(__nv_bfloat162*)(dsth + off) = __nv_bfloat162(h0, h1);
                    *(__nv_bfloat162*)(dstl + off) = __nv_bfloat162(l0, l1);
                }
            }
        }
    }
}

// ============================ V transpose ==================================
__global__ void __launch_bounds__(256)
vtrans_kernel(const __nv_bfloat16* __restrict__ Vh,
              const __nv_bfloat16* __restrict__ Vl,
              __nv_bfloat16* __restrict__ Vth,
              __nv_bfloat16* __restrict__ Vtl)
{
    __shared__ __nv_bfloat16 th[64 * 72], tl[64 * 72];
    const int bh = blockIdx.y, s0 = blockIdx.x * 64;
    const size_t ibase = (size_t)bh * SS * DD + (size_t)s0 * DD;
    #pragma unroll
    for (int i = 0; i < 2; i++) {
        const int idx = threadIdx.x + i * 256;
        const int r = idx >> 3, c = (idx & 7) * 8;
        *(uint4*)&th[r * 72 + c] = *(const uint4*)(Vh + ibase + (size_t)r * DD + c);
        *(uint4*)&tl[r * 72 + c] = *(const uint4*)(Vl + ibase + (size_t)r * DD + c);
    }
    __syncthreads();
    const size_t obase = (size_t)bh * DD * SS + s0;
    #pragma unroll
    for (int i = 0; i < 2; i++) {
        const int idx = threadIdx.x + i * 256;
        const int d = idx >> 3, c = (idx & 7) * 8;
        __nv_bfloat16 oh[8], ol[8];
        #pragma unroll
        for (int j = 0; j < 8; j++) {
            oh[j] = th[(c + j) * 72 + d];
            ol[j] = tl[(c + j) * 72 + d];
        }
        *(uint4*)(Vth + obase + (size_t)d * SS + c) = *(uint4*)oh;
        *(uint4*)(Vtl + obase + (size_t)d * SS + c) = *(uint4*)ol;
    }
}

// ============================ flash attention ==============================
// Per (bh, q-tile 128): warp = 16 q rows x full k.  For each 128-k tile:
// S = QK^T (3-product split MMA) -> e = exp(0.125 S) -> split A-frags ->
// O += e @ V via MMA with B from smem V^T.  Z accumulated; epilogue scales.
#define QSTR 72
#define KSTR 72
#define VSTR 136
#define FQPL (128 * QSTR * 2)          // 18432
#define FKPL (128 * KSTR * 2)          // 18432
#define FVPL (64 * VSTR * 2)           // 17408
#define FSTG (2 * FKPL + 2 * FVPL)     // 71680
#define FSOFF (2 * FQPL)               // 36864
#define FDSM (FSOFF + 2 * FSTG)        // 180224

__global__ void __launch_bounds__(256)
flash_kernel(const __nv_bfloat16* __restrict__ Qh,
             const __nv_bfloat16* __restrict__ Ql,
             const __nv_bfloat16* __restrict__ Kh,
             const __nv_bfloat16* __restrict__ Kl,
             const __nv_bfloat16* __restrict__ Vth,
             const __nv_bfloat16* __restrict__ Vtl,
             float* __restrict__ invz,
             __nv_bfloat16* __restrict__ Oh,
             __nv_bfloat16* __restrict__ Ol)
{
    extern __shared__ char dsm[];
    const uint32_t sb = smem_u32(dsm);
    const int tid = threadIdx.x;
    const int w = tid >> 5, lane = tid & 31;
    const int bh = blockIdx.y;
    const int b = bh >> 4, h = bh & 15;
    const int q0 = blockIdx.x * 128;
    const size_t base = (size_t)bh * SS * DD;
    const size_t vtbase = (size_t)bh * DD * SS;

    const int a_r = lane & 15;
    const int a_c = (lane >> 4) << 3;
    const int b_n = (lane & 7) + ((lane >> 4) & 1) * 8;
    const int b_k = ((lane >> 3) & 1) * 8;

    // ---- group 0: Q tile + k-tile 0 ----
    {
        const int r = tid >> 2, c16 = (tid & 3) << 4;
        #pragma unroll
        for (int u = 0; u < 2; u++) {
            const int rr = r + u * 64;
            const uint32_t so = (uint32_t)(rr * QSTR + c16) * 2;
            const size_t gq = base + (size_t)(q0 + rr) * DD + c16;
            CP16(sb + so,          Qh + gq);
            CP16(sb + so + 16,     Qh + gq + 8);
            CP16(sb + FQPL + so,      Ql + gq);
            CP16(sb + FQPL + so + 16, Ql + gq + 8);
        }
    }
    auto prefetch = [&](int kt, int stage) {
        const uint32_t s0 = sb + FSOFF + stage * FSTG;
        {   // K tile: 128 k-rows x 64 d
            const int r = tid >> 2, c16 = (tid & 3) << 4;
            #pragma unroll
            for (int u = 0; u < 2; u++) {
                const int rr = r + u * 64;
                const uint32_t so = (uint32_t)(rr * KSTR + c16) * 2;
                const size_t gk = base + (size_t)(kt * 128 + rr) * DD + c16;
                CP16(s0 + so,          Kh + gk);
                CP16(s0 + so + 16,     Kh + gk + 8);
                CP16(s0 + FKPL + so,      Kl + gk);
                CP16(s0 + FKPL + so + 16, Kl + gk + 8);
            }
        }
        {   // Vt tile: 64 d-rows x 128 k
            const int r = tid >> 3, c16 = (tid & 7) << 4;
            #pragma unroll
            for (int u = 0; u < 2; u++) {
                const int rr = r + u * 32;
                const uint32_t so = (uint32_t)(rr * VSTR + c16) * 2;
                const size_t gv = vtbase + (size_t)rr * SS + kt * 128 + c16;
                CP16(s0 + 2 * FKPL + so,          Vth + gv);
                CP16(s0 + 2 * FKPL + so + 16,     Vth + gv + 8);
                CP16(s0 + 2 * FKPL + FVPL + so,      Vtl + gv);
                CP16(s0 + 2 * FKPL + FVPL + so + 16, Vtl + gv + 8);
            }
        }
        CP_COMMIT();
    };

    prefetch(0, 0);
    CP_COMMIT();   // close group 0 (Q + stage0) -- note prefetch committed already; harmless empty group

    uint32_t aqh[4][4], aql[4][4];   // Q A-frags, 4 kd steps
    float O[8][4] = {};
    float zlo = 0.f, zhi = 0.f;

    for (int kt = 0; kt < 16; kt++) {
        const int stage = kt & 1;
        if (kt + 1 < 16) { prefetch(kt + 1, stage ^ 1); CP_WAIT1(); }
        else             { CP_WAIT0(); }
        __syncthreads();
        if (kt == 0) {
            #pragma unroll
            for (int kd = 0; kd < 4; kd++) {
                const uint32_t qa = (uint32_t)((w * 16 + a_r) * QSTR + kd * 16 + a_c) * 2;
                ldsm_x4(aqh[kd], sb + qa);
                ldsm_x4(aql[kd], sb + FQPL + qa);
            }
        }
        const uint32_t s0 = sb + FSOFF + stage * FSTG;

        #pragma unroll
        for (int t2 = 0; t2 < 8; t2++) {
            // ---- scores for k rows [t2*16, t2*16+16) ----
            float S0[4] = {}, S1[4] = {};
            #pragma unroll
            for (int kd = 0; kd < 4; kd++) {
                const uint32_t ka = (uint32_t)((t2 * 16 + b_n) * KSTR + kd * 16 + b_k) * 2;
                uint32_t th_[4], tl_[4];
                ldsm_x4(th_, s0 + ka);
                ldsm_x4(tl_, s0 + FKPL + ka);
                uint32_t bh0[2] = {th_[0], th_[1]}, bh1[2] = {th_[2], th_[3]};
                uint32_t bl0[2] = {tl_[0], tl_[1]}, bl1[2] = {tl_[2], tl_[3]};
                mma_bf16(S0, aqh[kd], bh0); mma_bf16(S0, aqh[kd], bl0); mma_bf16(S0, aql[kd], bh0);
                mma_bf16(S1, aqh[kd], bh1); mma_bf16(S1, aqh[kd], bl1); mma_bf16(S1, aql[kd], bh1);
            }
            // ---- e = exp(0.125 S), split to A-frags, Z accumulate ----
            uint32_t eh[4], el[4];
            {
                float e0 = expf(fminf(S0[0] * 0.125f, 60.f));
                float e1 = expf(fminf(S0[1] * 0.125f, 60.f));
                float e2 = expf(fminf(S0[2] * 0.125f, 60.f));
                float e3 = expf(fminf(S0[3] * 0.125f, 60.f));
                zlo += e0 + e1; zhi += e2 + e3;
                __nv_bfloat16 h0, h1, h2, h3, l0, l1, l2, l3;
                split2(e0, h0, l0); split2(e1, h1, l1);
                split2(e2, h2, l2); split2(e3, h3, l3);
                eh[0] = packbf(h0, h1); eh[1] = packbf(h2, h3);
                el[0] = packbf(l0, l1); el[1] = packbf(l2, l3);
                e0 = expf(fminf(S1[0] * 0.125f, 60.f));
                e1 = expf(fminf(S1[1] * 0.125f, 60.f));
                e2 = expf(fminf(S1[2] * 0.125f, 60.f));
                e3 = expf(fminf(S1[3] * 0.125f, 60.f));
                zlo += e0 + e1; zhi += e2 + e3;
                split2(e0, h0, l0); split2(e1, h1, l1);
                split2(e2, h2, l2); split2(e3, h3, l3);
                eh[2] = packbf(h0, h1); eh[3] = packbf(h2, h3);
                el[2] = packbf(l0, l1); el[3] = packbf(l2, l3);
            }
            // ---- AV: contraction chunk k16 = t2 ----
            #pragma unroll
            for (int d2 = 0; d2 < 4; d2++) {
                const uint32_t va = (uint32_t)((d2 * 16 + b_n) * VSTR + t2 * 16 + b_k) * 2;
                uint32_t th_[4], tl_[4];
                ldsm_x4(th_, s0 + 2 * FKPL + va);
                ldsm_x4(tl_, s0 + 2 * FKPL + FVPL + va);
                uint32_t bh0[2] = {th_[0], th_[1]}, bh1[2] = {th_[2], th_[3]};
                uint32_t bl0[2] = {tl_[0], tl_[1]}, bl1[2] = {tl_[2], tl_[3]};
                mma_bf16(O[2*d2],   eh, bh0); mma_bf16(O[2*d2],   eh, bl0); mma_bf16(O[2*d2],   el, bh0);
                mma_bf16(O[2*d2+1], eh, bh1); mma_bf16(O[2*d2+1], eh, bl1); mma_bf16(O[2*d2+1], el, bh1);
            }
        }
        __syncthreads();
    }

    // ---- Z reduce over the 4 lanes of each row group ----
    zlo += __shfl_xor_sync(0xffffffffu, zlo, 1);
    zlo += __shfl_xor_sync(0xffffffffu, zlo, 2);
    zhi += __shfl_xor_sync(0xffffffffu, zhi, 1);
    zhi += __shfl_xor_sync(0xffffffffu, zhi, 2);
    const int r4 = lane >> 2, c2 = (lane & 3) << 1;
    const int qa = q0 + w * 16 + r4, qb = qa + 8;
    const float iza = 1.0f / zlo, izb = 1.0f / zhi;
    if ((lane & 3) == 0) {
        invz[(bh << 11) + qa] = iza;
        invz[(bh << 11) + qb] = izb;
    }
    #pragma unroll
    for (int t = 0; t < 8; t++) {
        const int d = t * 8 + c2;
        const float v0 = O[t][0] * iza, v1 = O[t][1] * iza;
        const float v2 = O[t][2] * izb, v3 = O[t][3] * izb;
        __nv_bfloat16 h0, h1, l0, l1;
        split2(v0, h0, l0); split2(v1, h1, l1);
        const size_t offA = ((size_t)b * SS + qa) * EE + h * DD + d;
        *(__nv_bfloat162*)(Oh + offA) = __nv_bfloat162(h0, h1);
        *(__nv_bfloat162*)(Ol + offA) = __nv_bfloat162(l0, l1);
        split2(v2, h0, l0); split2(v3, h1, l1);
        const size_t offB = ((size_t)b * SS + qb) * EE + h * DD + d;
        *(__nv_bfloat162*)(Oh + offB) = __nv_bfloat162(h0, h1);
        *(__nv_bfloat162*)(Ol + offB) = __nv_bfloat162(l0, l1);
    }
}

// ============================ wout (mean of softmax) =======================
// Per (kt, qt, b): loops 16 heads through the scores pipeline, accumulating
// exp(score)*invz into wsum; writes wout = wsum/16.
__global__ void __launch_bounds__(256)
wout_kernel(const __nv_bfloat16* __restrict__ Qh,
            const __nv_bfloat16* __restrict__ Ql,
            const __nv_bfloat16* __restrict__ Kh,
            const __nv_bfloat16* __restrict__ Kl,
            const float* __restrict__ invz,
            float* __restrict__ wout)
{
    extern __shared__ char dsm[];
    __shared__ float iz[16][128];
    const uint32_t sb = smem_u32(dsm);
    const int tid = threadIdx.x;
    const int w = tid >> 5, lane = tid & 31;
    const int wm = w & 1, wn = w >> 1;
    const int k0t = blockIdx.x * 128;
    const int q0  = blockIdx.y * 128;
    const int b   = blockIdx.z;

    for (int i = tid; i < 2048; i += 256)
        iz[i >> 7][i & 127] = invz[((b * HH + (i >> 7)) << 11) + q0 + (i & 127)];

    const int a_r = lane & 15;
    const int a_c = (lane >> 4) << 3;
    const int b_n = (lane & 7) + ((lane >> 4) & 1) * 8;
    const int b_k = ((lane >> 3) & 1) * 8;
    const int ld_r  = tid >> 2;
    const int ld_c8 = (tid & 3) << 3;

    auto prefetch = [&](int it, int stage) {
        const int h = it >> 1;
        const int kc = (it & 1) * 32;
        const size_t hbase = (size_t)(b * HH + h) * SS * DD;
        const uint32_t s0 = sb + stage * GSTG;
        #pragma unroll
        for (int u = 0; u < 2; u++) {
            const int r = ld_r + u * 64;
            const uint32_t off = (uint32_t)(r * LDA + ld_c8) * 2;
            const size_t ga = hbase + (size_t)(q0 + r) * DD + kc + ld_c8;
            const size_t gb = hbase + (size_t)(k0t + r) * DD + kc + ld_c8;
            CP16(s0 + off,           Qh + ga);
            CP16(s0 + GPL + off,     Ql + ga);
            CP16(s0 + 2 * GPL + off, Kh + gb);
            CP16(s0 + 3 * GPL + off, Kl + gb);
        }
        CP_COMMIT();
    };

    float acc[4][4][4] = {};
    float wsum[4][4][4] = {};
    const int r4 = lane >> 2;

    prefetch(0, 0);
    for (int it = 0; it < 32; it++) {
        const int stage = it & 1;
        if (it + 1 < 32) { prefetch(it + 1, stage ^ 1); CP_WAIT1(); }
        else             { CP_WAIT0(); }
        __syncthreads();
        const uint32_t s0 = sb + stage * GSTG;
        #pragma unroll
        for (int ks = 0; ks < 32; ks += 16) {
            uint32_t bfh[4][2], bfl[4][2];
            #pragma unroll
            for (int pr = 0; pr < 2; pr++) {
                const int nrow = wn * 32 + pr * 16 + b_n;
                uint32_t t[4];
                ldsm_x4(t, s0 + 2 * GPL + (uint32_t)(nrow * LDA + ks + b_k) * 2);
                bfh[2*pr][0] = t[0]; bfh[2*pr][1] = t[1];
                bfh[2*pr+1][0] = t[2]; bfh[2*pr+1][1] = t[3];
                ldsm_x4(t, s0 + 3 * GPL + (uint32_t)(nrow * LDA + ks + b_k) * 2);
                bfl[2*pr][0] = t[0]; bfl[2*pr][1] = t[1];
                bfl[2*pr+1][0] = t[2]; bfl[2*pr+1][1] = t[3];
            }
            uint32_t af[4][4];
            #pragma unroll
            for (int mt = 0; mt < 4; mt++)
                ldsm_x4(af[mt], s0 + (uint32_t)((wm*64 + mt*16 + a_r) * LDA + ks + a_c) * 2);
            #pragma unroll
            for (int mt = 0; mt < 4; mt++)
                #pragma unroll
                for (int nt = 0; nt < 4; nt++) {
                    mma_bf16(acc[mt][nt], af[mt], bfh[nt]);
                    mma_bf16(acc[mt][nt], af[mt], bfl[nt]);
                }
            #pragma unroll
            for (int mt = 0; mt < 4; mt++)
                ldsm_x4(af[mt], s0 + GPL + (uint32_t)((wm*64 + mt*16 + a_r) * LDA + ks + a_c) * 2);
            #pragma unroll
            for (int mt = 0; mt < 4; mt++)
                #pragma unroll
                for (int nt = 0; nt < 4; nt++)
                    mma_bf16(acc[mt][nt], af[mt], bfh[nt]);
        }
        __syncthreads();
        if (it & 1) {
            const int h = it >> 1;
            #pragma unroll
            for (int mt = 0; mt < 4; mt++)
                #pragma unroll
                for (int rh = 0; rh < 2; rh++) {
                    const int qloc = wm * 64 + mt * 16 + rh * 8 + r4;
                    const float izv = iz[h][qloc];
                    #pragma unroll
                    for (int nt = 0; nt < 4; nt++) {
                        wsum[mt][nt][rh*2]   += expf(fminf(acc[mt][nt][rh*2]   * 0.125f, 60.f)) * izv;
                        wsum[mt][nt][rh*2+1] += expf(fminf(acc[mt][nt][rh*2+1] * 0.125f, 60.f)) * izv;
                        acc[mt][nt][rh*2] = 0.f; acc[mt][nt][rh*2+1] = 0.f;
                    }
                }
        }
    }

    const int c2 = (lane & 3) << 1;
    #pragma unroll
    for (int mt = 0; mt < 4; mt++) {
        #pragma unroll
        for (int rh = 0; rh < 2; rh++) {
            const int q = q0 + wm * 64 + mt * 16 + rh * 8 + r4;
            #pragma unroll
            for (int nt = 0; nt < 4; nt++) {
                const int kk = k0t + wn * 32 + nt * 8 + c2;
                *(float2*)(wout + ((size_t)(b * SS + q)) * SS + kk) =
                    make_float2(wsum[mt][nt][rh*2] * (1.0f / HH),
                                wsum[mt][nt][rh*2+1] * (1.0f / HH));
            }
        }
    }
}

// ---------------------------------------------------------------------------
extern "C" void kernel_launch(void* const* d_in, const int* in_sizes, int n_in,
                              void* d_out, int out_size)
{
    const float* query = (const float*)d_in[0];
    const float* key   = (const float*)d_in[1];
    const float* value = (const float*)d_in[2];
    const float* Win   = (const float*)d_in[3];
    const float* bin   = (const float*)d_in[4];
    const float* Wout  = (const float*)d_in[5];
    const float* bout  = (const float*)d_in[6];

    float* out  = (float*)d_out;
    float* wout = out + (size_t)BB * SS * EE;

    __nv_bfloat16 *xqh, *xql, *xkh, *xkl, *xvh, *xvl, *wh, *wl, *woh, *wol;
    __nv_bfloat16 *qh, *ql, *kh, *kl, *vh, *vl, *vth, *vtl, *ah, *al;
    float* invz;
    cudaGetSymbolAddress((void**)&xqh, g_xqh);
    cudaGetSymbolAddress((void**)&xql, g_xql);
    cudaGetSymbolAddress((void**)&xkh, g_xkh);
    cudaGetSymbolAddress((void**)&xkl, g_xkl);
    cudaGetSymbolAddress((void**)&xvh, g_xvh);
    cudaGetSymbolAddress((void**)&xvl, g_xvl);
    cudaGetSymbolAddress((void**)&wh,  g_wh);
    cudaGetSymbolAddress((void**)&wl,  g_wl);
    cudaGetSymbolAddress((void**)&woh, g_woh);
    cudaGetSymbolAddress((void**)&wol, g_wol);
    cudaGetSymbolAddress((void**)&qh,  g_qh);
    cudaGetSymbolAddress((void**)&ql,  g_ql);
    cudaGetSymbolAddress((void**)&kh,  g_kh);
    cudaGetSymbolAddress((void**)&kl,  g_kl);
    cudaGetSymbolAddress((void**)&vh,  g_vh);
    cudaGetSymbolAddress((void**)&vl,  g_vl);
    cudaGetSymbolAddress((void**)&vth, g_vth);
    cudaGetSymbolAddress((void**)&vtl, g_vtl);
    cudaGetSymbolAddress((void**)&ah,  g_ah);
    cudaGetSymbolAddress((void**)&al,  g_al);
    cudaGetSymbolAddress((void**)&invz, g_invz);

    cudaFuncSetAttribute(gemm_split_kernel,
                         cudaFuncAttributeMaxDynamicSharedMemorySize, GDSM);
    cudaFuncSetAttribute(flash_kernel,
                         cudaFuncAttributeMaxDynamicSharedMemorySize, FDSM);
    cudaFuncSetAttribute(wout_kernel,
                         cudaFuncAttributeMaxDynamicSharedMemorySize, GDSM);

    // splits of inputs + weights
    split_kernel<<<(MROWS * EE / 4 + 255) / 256, 256>>>(query, xqh, xql, MROWS * EE / 4);
    split_kernel<<<(MROWS * EE / 4 + 255) / 256, 256>>>(key,   xkh, xkl, MROWS * EE / 4);
    split_kernel<<<(MROWS * EE / 4 + 255) / 256, 256>>>(value, xvh, xvl, MROWS * EE / 4);
    split_kernel<<<(3 * EE * EE / 4 + 255) / 256, 256>>>(Win,  wh,  wl,  3 * EE * EE / 4);
    split_kernel<<<(EE * EE / 4 + 255) / 256, 256>>>(Wout, woh, wol, EE * EE / 4);

    // projections (RoPE fused for q,k)
    dim3 gg(EE / 128, MROWS / 128);
    gemm_split_kernel<<<gg, 256, GDSM>>>(xqh, xql, wh,                   wl,                   bin,        nullptr, qh, ql, 2);
    gemm_split_kernel<<<gg, 256, GDSM>>>(xkh, xkl, wh + (size_t)EE*EE,   wl + (size_t)EE*EE,   bin + EE,   nullptr, kh, kl, 2);
    gemm_split_kernel<<<gg, 256, GDSM>>>(xvh, xvl, wh + 2*(size_t)EE*EE, wl + 2*(size_t)EE*EE, bin + 2*EE, nullptr, vh, vl, 1);

    // V transpose
    dim3 gt(SS / 64, BB * HH);
    vtrans_kernel<<<gt, 256>>>(vh, vl, vth, vtl);

    // fused attention: O (att planes) + invz; no P materialization
    dim3 gf(SS / 128, BB * HH);
    flash_kernel<<<gf, 256, FDSM>>>(qh, ql, kh, kl, vth, vtl, invz, ah, al);

    // wout = head-mean of softmax (scores recomputed)
    dim3 gw(SS / 128, SS / 128, BB);
    wout_kernel<<<gw, 256, GDSM>>>(qh, ql, kh, kl, invz, wout);

    // out projection
    gemm_split_kernel<<<gg, 256, GDSM>>>(ah, al, woh, wol, bout, out, nullptr, nullptr, 0);
}

// round 17
// speedup vs baseline: 1.0664x; 1.0664x over previous
#include <cuda_runtime.h>
#include <cuda_bf16.h>
#include <math.h>
#include <math_constants.h>
#include <cstdint>

#define BB 4
#define SS 2048
#define EE 1024
#define HH 16
#define DD 64
#define MROWS (BB*SS)          // 8192

// -------- device scratch (statically allocated; no cudaMalloc allowed) -----
__device__ float g_p[268435456];        // [B,H,S,S] fp32 scores (1 GB)

__device__ __nv_bfloat16 g_xqh[8388608], g_xql[8388608];
__device__ __nv_bfloat16 g_xkh[8388608], g_xkl[8388608];
__device__ __nv_bfloat16 g_xvh[8388608], g_xvl[8388608];
__device__ __nv_bfloat16 g_wh[3145728],  g_wl[3145728];    // in_proj W [3E,E]
__device__ __nv_bfloat16 g_woh[1048576], g_wol[1048576];   // out_proj W [E,E]
__device__ __nv_bfloat16 g_qh[8388608],  g_ql[8388608];
__device__ __nv_bfloat16 g_kh[8388608],  g_kl[8388608];
__device__ __nv_bfloat16 g_vh[8388608],  g_vl[8388608];
__device__ __nv_bfloat16 g_vth[8388608], g_vtl[8388608];   // V^T [B,H,D,S]
__device__ __nv_bfloat16 g_ph[268435456], g_pl[268435456]; // probs split
__device__ __nv_bfloat16 g_ah[8388608],  g_al[8388608];    // att split

// ============================ PTX helpers ==================================
__device__ __forceinline__ uint32_t smem_u32(const void* p) {
    uint32_t a;
    asm("{ .reg .u64 t; cvta.to.shared.u64 t, %1; cvt.u32.u64 %0, t; }"
        : "=r"(a) : "l"(p));
    return a;
}
__device__ __forceinline__ void ldsm_x4(uint32_t* r, uint32_t addr) {
    asm volatile("ldmatrix.sync.aligned.m8n8.x4.shared.b16 {%0,%1,%2,%3}, [%4];"
        : "=r"(r[0]), "=r"(r[1]), "=r"(r[2]), "=r"(r[3]) : "r"(addr));
}
__device__ __forceinline__ void mma_bf16(float* d, const uint32_t* a, const uint32_t* b) {
    asm volatile("mma.sync.aligned.m16n8k16.row.col.f32.bf16.bf16.f32 "
        "{%0,%1,%2,%3}, {%4,%5,%6,%7}, {%8,%9}, {%0,%1,%2,%3};"
        : "+f"(d[0]), "+f"(d[1]), "+f"(d[2]), "+f"(d[3])
        : "r"(a[0]), "r"(a[1]), "r"(a[2]), "r"(a[3]), "r"(b[0]), "r"(b[1]));
}
__device__ __forceinline__ void split2(float v, __nv_bfloat16& h, __nv_bfloat16& l) {
    h = __float2bfloat16_rn(v);
    l = __float2bfloat16_rn(v - __bfloat162float(h));
}
__device__ __forceinline__ uint32_t packbf(__nv_bfloat16 a, __nv_bfloat16 b) {
    return (uint32_t)__bfloat16_as_ushort(a) | ((uint32_t)__bfloat16_as_ushort(b) << 16);
}
#define CP16(dst, src) \
    asm volatile("cp.async.cg.shared.global [%0], [%1], 16;" :: "r"(dst), "l"(src))
#define CP_COMMIT() asm volatile("cp.async.commit_group;" ::: "memory")
#define CP_WAIT1()  asm volatile("cp.async.wait_group 1;" ::: "memory")
#define CP_WAIT0()  asm volatile("cp.async.wait_group 0;" ::: "memory")

#define LDA 40   // smem row stride in halves (80B -> conflict-free LDSM)

// ============================ split kernel =================================
__global__ void __launch_bounds__(256)
split_kernel(const float* __restrict__ src,
             __nv_bfloat16* __restrict__ hi,
             __nv_bfloat16* __restrict__ lo, int n4)
{
    int i = blockIdx.x * 256 + threadIdx.x;
    if (i >= n4) return;
    float4 x = ((const float4*)src)[i];
    __nv_bfloat16 h0, h1, h2, h3, l0, l1, l2, l3;
    split2(x.x, h0, l0); split2(x.y, h1, l1);
    split2(x.z, h2, l2); split2(x.w, h3, l3);
    uint2 hv, lv;
    hv.x = packbf(h0, h1); hv.y = packbf(h2, h3);
    lv.x = packbf(l0, l1); lv.y = packbf(l2, l3);
    *(uint2*)(hi + (size_t)i * 4) = hv;
    *(uint2*)(lo + (size_t)i * 4) = lv;
}

// ============================ HMMA GEMM (projections) ======================
#define GPL  (128 * LDA * 2)     // 10240 B per plane
#define GSTG (4 * GPL)           // 40960 B per stage
#define GDSM (2 * GSTG)          // 81920 B

__global__ void __launch_bounds__(256)
gemm_split_kernel(const __nv_bfloat16* __restrict__ Ah_,
                  const __nv_bfloat16* __restrict__ Al_,
                  const __nv_bfloat16* __restrict__ Bh_,
                  const __nv_bfloat16* __restrict__ Bl_,
                  const float* __restrict__ bias,
                  float* __restrict__ dst32,
                  __nv_bfloat16* __restrict__ dsth,
                  __nv_bfloat16* __restrict__ dstl, int mode)
{
    extern __shared__ char dsm[];
    const uint32_t sb = smem_u32(dsm);
    const int tid = threadIdx.x;
    const int w = tid >> 5, lane = tid & 31;
    const int wm = w & 1, wn = w >> 1;
    const int row0 = blockIdx.y * 128, col0 = blockIdx.x * 128;

    float acc[4][4][4] = {};

    const int a_r = lane & 15;
    const int a_c = (lane >> 4) << 3;
    const int b_n = (lane & 7) + ((lane >> 4) & 1) * 8;
    const int b_k = ((lane >> 3) & 1) * 8;
    const int ld_r  = tid >> 2;
    const int ld_c8 = (tid & 3) << 3;

    auto prefetch = [&](int it, int stage) {
        const int k0 = it * 32;
        const uint32_t s0 = sb + stage * GSTG;
        #pragma unroll
        for (int u = 0; u < 2; u++) {
            const int r = ld_r + u * 64;
            const uint32_t off = (uint32_t)(r * LDA + ld_c8) * 2;
            const size_t ga = (size_t)(row0 + r) * EE + k0 + ld_c8;
            const size_t gb = (size_t)(col0 + r) * EE + k0 + ld_c8;
            CP16(s0 + off,           Ah_ + ga);
            CP16(s0 + GPL + off,     Al_ + ga);
            CP16(s0 + 2 * GPL + off, Bh_ + gb);
            CP16(s0 + 3 * GPL + off, Bl_ + gb);
        }
        CP_COMMIT();
    };

    prefetch(0, 0);
    for (int it = 0; it < 32; it++) {
        const int stage = it & 1;
        if (it + 1 < 32) { prefetch(it + 1, stage ^ 1); CP_WAIT1(); }
        else             { CP_WAIT0(); }
        __syncthreads();
        const uint32_t s0 = sb + stage * GSTG;
        #pragma unroll
        for (int ks = 0; ks < 32; ks += 16) {
            uint32_t bfh[4][2], bfl[4][2];
            #pragma unroll
            for (int pr = 0; pr < 2; pr++) {
                const int nrow = wn * 32 + pr * 16 + b_n;
                uint32_t t[4];
                ldsm_x4(t, s0 + 2 * GPL + (uint32_t)(nrow * LDA + ks + b_k) * 2);
                bfh[2*pr][0] = t[0]; bfh[2*pr][1] = t[1];
                bfh[2*pr+1][0] = t[2]; bfh[2*pr+1][1] = t[3];
                ldsm_x4(t, s0 + 3 * GPL + (uint32_t)(nrow * LDA + ks + b_k) * 2);
                bfl[2*pr][0] = t[0]; bfl[2*pr][1] = t[1];
                bfl[2*pr+1][0] = t[2]; bfl[2*pr+1][1] = t[3];
            }
            uint32_t af[4][4];
            #pragma unroll
            for (int mt = 0; mt < 4; mt++)
                ldsm_x4(af[mt], s0 + (uint32_t)((wm*64 + mt*16 + a_r) * LDA + ks + a_c) * 2);
            #pragma unroll
            for (int mt = 0; mt < 4; mt++)
                #pragma unroll
                for (int nt = 0; nt < 4; nt++) {
                    mma_bf16(acc[mt][nt], af[mt], bfh[nt]);
                    mma_bf16(acc[mt][nt], af[mt], bfl[nt]);
                }
            #pragma unroll
            for (int mt = 0; mt < 4; mt++)
                ldsm_x4(af[mt], s0 + GPL + (uint32_t)((wm*64 + mt*16 + a_r) * LDA + ks + a_c) * 2);
            #pragma unroll
            for (int mt = 0; mt < 4; mt++)
                #pragma unroll
                for (int nt = 0; nt < 4; nt++)
                    mma_bf16(acc[mt][nt], af[mt], bfh[nt]);
        }
        __syncthreads();
    }

    const int r4 = lane >> 2, c2 = (lane & 3) << 1;
    float bs0[4], bs1[4], invs[4];
    #pragma unroll
    for (int nt = 0; nt < 4; nt++) {
        const int col = col0 + wn * 32 + nt * 8 + c2;
        bs0[nt] = bias[col];
        bs1[nt] = bias[col + 1];
        invs[nt] = expf(-(float)((col & 63) >> 1) * 0.28782313662425567f);
    }

    #pragma unroll
    for (int mt = 0; mt < 4; mt++) {
        #pragma unroll
        for (int rh = 0; rh < 2; rh++) {
            const int m = row0 + wm * 64 + mt * 16 + rh * 8 + r4;
            const int b = m >> 11, s = m & 2047;
            #pragma unroll
            for (int nt = 0; nt < 4; nt++) {
                const int col = col0 + wn * 32 + nt * 8 + c2;
                float v0 = acc[mt][nt][rh * 2 + 0] + bs0[nt];
                float v1 = acc[mt][nt][rh * 2 + 1] + bs1[nt];
                if (mode == 0) {
                    *(float2*)(dst32 + (size_t)m * EE + col) = make_float2(v0, v1);
                } else {
                    if (mode == 2) {
                        float sn, cs;
                        sincosf((float)s * invs[nt], &sn, &cs);
                        const float t0 = v0, t1 = v1;
                        v0 = t0 * cs - t1 * sn;
                        v1 = t1 * cs + t0 * sn;
                    }
                    const int h = col >> 6, d0 = col & 63;
                    const size_t off = ((size_t)(b * HH + h) * SS + s) * DD + d0;
                    __nv_bfloat16 h0, h1, l0, l1;
                    split2(v0, h0, l0); split2(v1, h1, l1);
                    *(__nv_bfloat162*)(dsth + off) = __nv_bfloat162(h0, h1);
                    *(__nv_bfloat162*)(dstl + off) = __nv_bfloat162(l0, l1);
                }
            }
        }
    }
}

// ============================ V transpose ==================================
__global__ void __launch_bounds__(256)
vtrans_kernel(const __nv_bfloat16* __restrict__ Vh,
              const __nv_bfloat16* __restrict__ Vl,
              __nv_bfloat16* __restrict__ Vth,
              __nv_bfloat16* __restrict__ Vtl)
{
    __shared__ __nv_bfloat16 th[64 * 72], tl[64 * 72];
    const int bh = blockIdx.y, s0 = blockIdx.x * 64;
    const size_t ibase = (size_t)bh * SS * DD + (size_t)s0 * DD;
    #pragma unroll
    for (int i = 0; i < 2; i++) {
        const int idx = threadIdx.x + i * 256;
        const int r = idx >> 3, c = (idx & 7) * 8;
        *(uint4*)&th[r * 72 + c] = *(const uint4*)(Vh + ibase + (size_t)r * DD + c);
        *(uint4*)&tl[r * 72 + c] = *(const uint4*)(Vl + ibase + (size_t)r * DD + c);
    }
    __syncthreads();
    const size_t obase = (size_t)bh * DD * SS + s0;
    #pragma unroll
    for (int i = 0; i < 2; i++) {
        const int idx = threadIdx.x + i * 256;
        const int d = idx >> 3, c = (idx & 7) * 8;
        __nv_bfloat16 oh[8], ol[8];
        #pragma unroll
        for (int j = 0; j < 8; j++) {
            oh[j] = th[(c + j) * 72 + d];
            ol[j] = tl[(c + j) * 72 + d];
        }
        *(uint4*)(Vth + obase + (size_t)d * SS + c) = *(uint4*)oh;
        *(uint4*)(Vtl + obase + (size_t)d * SS + c) = *(uint4*)ol;
    }
}

// ============================ scores HMMA ==================================
// P[bh,q,k] = 0.125 * sum_d Q.K  (fp32 out, float2 stores)
__global__ void __launch_bounds__(256)
scores_hmma_kernel(const __nv_bfloat16* __restrict__ Qh,
                   const __nv_bfloat16* __restrict__ Ql,
                   const __nv_bfloat16* __restrict__ Kh,
                   const __nv_bfloat16* __restrict__ Kl,
                   float* __restrict__ P)
{
    extern __shared__ char dsm[];
    const uint32_t sb = smem_u32(dsm);
    const int tid = threadIdx.x;
    const int w = tid >> 5, lane = tid & 31;
    const int wm = w & 1, wn = w >> 1;
    const int bh = blockIdx.z;
    const int q0 = blockIdx.y * 128, k0t = blockIdx.x * 128;
    const size_t base = (size_t)bh * SS * DD;

    float acc[4][4][4] = {};

    const int a_r = lane & 15;
    const int a_c = (lane >> 4) << 3;
    const int b_n = (lane & 7) + ((lane >> 4) & 1) * 8;
    const int b_k = ((lane >> 3) & 1) * 8;
    const int ld_r  = tid >> 2;
    const int ld_c8 = (tid & 3) << 3;

    auto prefetch = [&](int it, int stage) {
        const int kc = it * 32;
        const uint32_t s0 = sb + stage * GSTG;
        #pragma unroll
        for (int u = 0; u < 2; u++) {
            const int r = ld_r + u * 64;
            const uint32_t off = (uint32_t)(r * LDA + ld_c8) * 2;
            const size_t ga = base + (size_t)(q0 + r) * DD + kc + ld_c8;
            const size_t gb = base + (size_t)(k0t + r) * DD + kc + ld_c8;
            CP16(s0 + off,           Qh + ga);
            CP16(s0 + GPL + off,     Ql + ga);
            CP16(s0 + 2 * GPL + off, Kh + gb);
            CP16(s0 + 3 * GPL + off, Kl + gb);
        }
        CP_COMMIT();
    };

    prefetch(0, 0);
    for (int it = 0; it < 2; it++) {
        const int stage = it & 1;
        if (it + 1 < 2) { prefetch(it + 1, stage ^ 1); CP_WAIT1(); }
        else            { CP_WAIT0(); }
        __syncthreads();
        const uint32_t s0 = sb + stage * GSTG;
        #pragma unroll
        for (int ks = 0; ks < 32; ks += 16) {
            uint32_t bfh[4][2], bfl[4][2];
            #pragma unroll
            for (int pr = 0; pr < 2; pr++) {
                const int nrow = wn * 32 + pr * 16 + b_n;
                uint32_t t[4];
                ldsm_x4(t, s0 + 2 * GPL + (uint32_t)(nrow * LDA + ks + b_k) * 2);
                bfh[2*pr][0] = t[0]; bfh[2*pr][1] = t[1];
                bfh[2*pr+1][0] = t[2]; bfh[2*pr+1][1] = t[3];
                ldsm_x4(t, s0 + 3 * GPL + (uint32_t)(nrow * LDA + ks + b_k) * 2);
                bfl[2*pr][0] = t[0]; bfl[2*pr][1] = t[1];
                bfl[2*pr+1][0] = t[2]; bfl[2*pr+1][1] = t[3];
            }
            uint32_t af[4][4];
            #pragma unroll
            for (int mt = 0; mt < 4; mt++)
                ldsm_x4(af[mt], s0 + (uint32_t)((wm*64 + mt*16 + a_r) * LDA + ks + a_c) * 2);
            #pragma unroll
            for (int mt = 0; mt < 4; mt++)
                #pragma unroll
                for (int nt = 0; nt < 4; nt++) {
                    mma_bf16(acc[mt][nt], af[mt], bfh[nt]);
                    mma_bf16(acc[mt][nt], af[mt], bfl[nt]);
                }
            #pragma unroll
            for (int mt = 0; mt < 4; mt++)
                ldsm_x4(af[mt], s0 + GPL + (uint32_t)((wm*64 + mt*16 + a_r) * LDA + ks + a_c) * 2);
            #pragma unroll
            for (int mt = 0; mt < 4; mt++)
                #pragma unroll
                for (int nt = 0; nt < 4; nt++)
                    mma_bf16(acc[mt][nt], af[mt], bfh[nt]);
        }
        __syncthreads();
    }

    const int r4 = lane >> 2, c2 = (lane & 3) << 1;
    const size_t pbase = (size_t)bh * SS * SS;
    #pragma unroll
    for (int mt = 0; mt < 4; mt++) {
        #pragma unroll
        for (int rh = 0; rh < 2; rh++) {
            const int q = q0 + wm * 64 + mt * 16 + rh * 8 + r4;
            #pragma unroll
            for (int nt = 0; nt < 4; nt++) {
                const int kk = k0t + wn * 32 + nt * 8 + c2;
                *(float2*)(P + pbase + (size_t)q * SS + kk) =
                    make_float2(acc[mt][nt][rh*2] * 0.125f, acc[mt][nt][rh*2+1] * 0.125f);
            }
        }
    }
}

// ---------------------------------------------------------------------------
// fused softmax + head-mean.  No-max clamped exp (validated R9/R12/R13),
// single sum-reduction per head, double-buffered reduction slots:
// 2 block syncs per head (vs ~5 with the max pass).
// ---------------------------------------------------------------------------
__global__ void __launch_bounds__(256)
softmax_mean_kernel(const float* __restrict__ P,
                    __nv_bfloat16* __restrict__ Ph,
                    __nv_bfloat16* __restrict__ Pl,
                    float* __restrict__ wout)
{
    const int bq = blockIdx.x;
    const int b = bq >> 11, q = bq & 2047;
    const int tid = threadIdx.x;
    const int lane = tid & 31, warp = tid >> 5;
    __shared__ float red[2][8];
    __shared__ float redz[2];

    float macc[8] = {};

    for (int h = 0; h < HH; h++) {
        const int buf = h & 1;
        const size_t rowoff = ((size_t)(b * HH + h) * SS + q) * SS;
        const float* p = P + rowoff;

        float v[8];
        float sum = 0.f;
        #pragma unroll
        for (int i = 0; i < 8; i++) {
            v[i] = expf(fminf(p[tid + (i << 8)], 60.f));
            sum += v[i];
        }
        #pragma unroll
        for (int o = 16; o; o >>= 1) sum += __shfl_xor_sync(0xffffffffu, sum, o);
        if (lane == 0) red[buf][warp] = sum;
        __syncthreads();
        if (tid < 32) {
            float t = (tid < 8) ? red[buf][tid] : 0.f;
            #pragma unroll
            for (int o = 4; o; o >>= 1) t += __shfl_xor_sync(0xffffffffu, t, o);
            if (tid == 0) redz[buf] = t;
        }
        __syncthreads();
        const float inv = 1.0f / redz[buf];

        #pragma unroll
        for (int i = 0; i < 8; i++) {
            v[i] *= inv;
            __nv_bfloat16 hi, lo;
            split2(v[i], hi, lo);
            Ph[rowoff + tid + (i << 8)] = hi;
            Pl[rowoff + tid + (i << 8)] = lo;
            macc[i] += v[i];
        }
        // no sync needed: next head writes the OTHER red/redz buffer
    }

    float* wo = wout + (size_t)bq * SS;
    #pragma unroll
    for (int i = 0; i < 8; i++) wo[tid + (i << 8)] = macc[i] * (1.0f / HH);
}

// ============================ av HMMA ======================================
#define APL  (128 * LDA * 2)           // 10240
#define BPL  (64 * LDA * 2)            // 5120
#define ASTG (2 * APL + 2 * BPL)       // 30720
#define ADSM (2 * ASTG)                // 61440

__global__ void __launch_bounds__(256)
av_hmma_kernel(const __nv_bfloat16* __restrict__ Ph,
               const __nv_bfloat16* __restrict__ Pl,
               const __nv_bfloat16* __restrict__ Vth,
               const __nv_bfloat16* __restrict__ Vtl,
               __nv_bfloat16* __restrict__ Oh,
               __nv_bfloat16* __restrict__ Ol)
{
    extern __shared__ char dsm[];
    const uint32_t sb = smem_u32(dsm);
    const int tid = threadIdx.x;
    const int w = tid >> 5, lane = tid & 31;
    const int wm = w & 1, wn = w >> 1;
    const int bh = blockIdx.y;
    const int b = bh >> 4, h = bh & 15;
    const int q0 = blockIdx.x * 128;
    const size_t pbase = (size_t)bh * SS * SS;
    const size_t vtbase = (size_t)bh * DD * SS;

    float acc[4][2][4] = {};

    const int a_r = lane & 15;
    const int a_c = (lane >> 4) << 3;
    const int b_n = (lane & 7) + ((lane >> 4) & 1) * 8;
    const int b_k = ((lane >> 3) & 1) * 8;
    const int ld_r  = tid >> 2;
    const int ld_c8 = (tid & 3) << 3;

    auto prefetch = [&](int it, int stage) {
        const int k0 = it * 32;
        const uint32_t s0 = sb + stage * ASTG;
        #pragma unroll
        for (int u = 0; u < 2; u++) {
            const int r = ld_r + u * 64;
            const uint32_t off = (uint32_t)(r * LDA + ld_c8) * 2;
            const size_t ga = pbase + (size_t)(q0 + r) * SS + k0 + ld_c8;
            CP16(s0 + off,       Ph + ga);
            CP16(s0 + APL + off, Pl + ga);
        }
        {
            const uint32_t off = (uint32_t)(ld_r * LDA + ld_c8) * 2;
            const size_t gb = vtbase + (size_t)ld_r * SS + k0 + ld_c8;
            CP16(s0 + 2 * APL + off,       Vth + gb);
            CP16(s0 + 2 * APL + BPL + off, Vtl + gb);
        }
        CP_COMMIT();
    };

    prefetch(0, 0);
    for (int it = 0; it < 64; it++) {
        const int stage = it & 1;
        if (it + 1 < 64) { prefetch(it + 1, stage ^ 1); CP_WAIT1(); }
        else             { CP_WAIT0(); }
        __syncthreads();
        const uint32_t s0 = sb + stage * ASTG;
        #pragma unroll
        for (int ks = 0; ks < 32; ks += 16) {
            uint32_t bfh[2][2], bfl[2][2];
            {
                const int nrow = wn * 16 + b_n;
                uint32_t t[4];
                ldsm_x4(t, s0 + 2 * APL + (uint32_t)(nrow * LDA + ks + b_k) * 2);
                bfh[0][0] = t[0]; bfh[0][1] = t[1];
                bfh[1][0] = t[2]; bfh[1][1] = t[3];
                ldsm_x4(t, s0 + 2 * APL + BPL + (uint32_t)(nrow * LDA + ks + b_k) * 2);
                bfl[0][0] = t[0]; bfl[0][1] = t[1];
                bfl[1][0] = t[2]; bfl[1][1] = t[3];
            }
            uint32_t af[4][4];
            #pragma unroll
            for (int mt = 0; mt < 4; mt++)
                ldsm_x4(af[mt], s0 + (uint32_t)((wm*64 + mt*16 + a_r) * LDA + ks + a_c) * 2);
            #pragma unroll
            for (int mt = 0; mt < 4; mt++)
                #pragma unroll
                for (int nt = 0; nt < 2; nt++) {
                    mma_bf16(acc[mt][nt], af[mt], bfh[nt]);
                    mma_bf16(acc[mt][nt], af[mt], bfl[nt]);
                }
            #pragma unroll
            for (int mt = 0; mt < 4; mt++)
                ldsm_x4(af[mt], s0 + APL + (uint32_t)((wm*64 + mt*16 + a_r) * LDA + ks + a_c) * 2);
            #pragma unroll
            for (int mt = 0; mt < 4; mt++)
                #pragma unroll
                for (int nt = 0; nt < 2; nt++)
                    mma_bf16(acc[mt][nt], af[mt], bfh[nt]);
        }
        __syncthreads();
    }

    const int r4 = lane >> 2, c2 = (lane & 3) << 1;
    #pragma unroll
    for (int mt = 0; mt < 4; mt++) {
        #pragma unroll
        for (int rh = 0; rh < 2; rh++) {
            const int s = q0 + wm * 64 + mt * 16 + rh * 8 + r4;
            #pragma unroll
            for (int nt = 0; nt < 2; nt++) {
                const int d = wn * 16 + nt * 8 + c2;
                const float v0 = acc[mt][nt][rh*2];
                const float v1 = acc[mt][nt][rh*2+1];
                __nv_bfloat16 h0, h1, l0, l1;
                split2(v0, h0, l0); split2(v1, h1, l1);
                const size_t off = ((size_t)b * SS + s) * EE + h * DD + d;
                *(__nv_bfloat162*)(Oh + off) = __nv_bfloat162(h0, h1);
                *(__nv_bfloat162*)(Ol + off) = __nv_bfloat162(l0, l1);
            }
        }
    }
}

// ---------------------------------------------------------------------------
extern "C" void kernel_launch(void* const* d_in, const int* in_sizes, int n_in,
                              void* d_out, int out_size)
{
    const float* query = (const float*)d_in[0];
    const float* key   = (const float*)d_in[1];
    const float* value = (const float*)d_in[2];
    const float* Win   = (const float*)d_in[3];
    const float* bin   = (const float*)d_in[4];
    const float* Wout  = (const float*)d_in[5];
    const float* bout  = (const float*)d_in[6];

    float* out  = (float*)d_out;
    float* wout = out + (size_t)BB * SS * EE;

    float* pp;
    cudaGetSymbolAddress((void**)&pp, g_p);

    __nv_bfloat16 *xqh, *xql, *xkh, *xkl, *xvh, *xvl, *wh, *wl, *woh, *wol;
    __nv_bfloat16 *qh, *ql, *kh, *kl, *vh, *vl, *vth, *vtl, *ph, *pl, *ah, *al;
    cudaGetSymbolAddress((void**)&xqh, g_xqh);
    cudaGetSymbolAddress((void**)&xql, g_xql);
    cudaGetSymbolAddress((void**)&xkh, g_xkh);
    cudaGetSymbolAddress((void**)&xkl, g_xkl);
    cudaGetSymbolAddress((void**)&xvh, g_xvh);
    cudaGetSymbolAddress((void**)&xvl, g_xvl);
    cudaGetSymbolAddress((void**)&wh,  g_wh);
    cudaGetSymbolAddress((void**)&wl,  g_wl);
    cudaGetSymbolAddress((void**)&woh, g_woh);
    cudaGetSymbolAddress((void**)&wol, g_wol);
    cudaGetSymbolAddress((void**)&qh,  g_qh);
    cudaGetSymbolAddress((void**)&ql,  g_ql);
    cudaGetSymbolAddress((void**)&kh,  g_kh);
    cudaGetSymbolAddress((void**)&kl,  g_kl);
    cudaGetSymbolAddress((void**)&vh,  g_vh);
    cudaGetSymbolAddress((void**)&vl,  g_vl);
    cudaGetSymbolAddress((void**)&vth, g_vth);
    cudaGetSymbolAddress((void**)&vtl, g_vtl);
    cudaGetSymbolAddress((void**)&ph,  g_ph);
    cudaGetSymbolAddress((void**)&pl,  g_pl);
    cudaGetSymbolAddress((void**)&ah,  g_ah);
    cudaGetSymbolAddress((void**)&al,  g_al);

    cudaFuncSetAttribute(gemm_split_kernel,
                         cudaFuncAttributeMaxDynamicSharedMemorySize, GDSM);
    cudaFuncSetAttribute(scores_hmma_kernel,
                         cudaFuncAttributeMaxDynamicSharedMemorySize, GDSM);
    cudaFuncSetAttribute(av_hmma_kernel,
                         cudaFuncAttributeMaxDynamicSharedMemorySize, ADSM);

    // splits of inputs + weights
    split_kernel<<<(MROWS * EE / 4 + 255) / 256, 256>>>(query, xqh, xql, MROWS * EE / 4);
    split_kernel<<<(MROWS * EE / 4 + 255) / 256, 256>>>(key,   xkh, xkl, MROWS * EE / 4);
    split_kernel<<<(MROWS * EE / 4 + 255) / 256, 256>>>(value, xvh, xvl, MROWS * EE / 4);
    split_kernel<<<(3 * EE * EE / 4 + 255) / 256, 256>>>(Win,  wh,  wl,  3 * EE * EE / 4);
    split_kernel<<<(EE * EE / 4 + 255) / 256, 256>>>(Wout, woh, wol, EE * EE / 4);

    // projections (RoPE fused for q,k)
    dim3 gg(EE / 128, MROWS / 128);
    gemm_split_kernel<<<gg, 256, GDSM>>>(xqh, xql, wh,                   wl,                   bin,        nullptr, qh, ql, 2);
    gemm_split_kernel<<<gg, 256, GDSM>>>(xkh, xkl, wh + (size_t)EE*EE,   wl + (size_t)EE*EE,   bin + EE,   nullptr, kh, kl, 2);
    gemm_split_kernel<<<gg, 256, GDSM>>>(xvh, xvl, wh + 2*(size_t)EE*EE, wl + 2*(size_t)EE*EE, bin + 2*EE, nullptr, vh, vl, 1);

    // V transpose
    dim3 gt(SS / 64, BB * HH);
    vtrans_kernel<<<gt, 256>>>(vh, vl, vth, vtl);

    // scores -> fp32 P
    dim3 gs(SS / 128, SS / 128, BB * HH);
    scores_hmma_kernel<<<gs, 256, GDSM>>>(qh, ql, kh, kl, pp);

    // softmax + head mean (no-max clamped exp; probs -> split planes)
    softmax_mean_kernel<<<BB * SS, 256>>>(pp, ph, pl, wout);

    // attn @ V
    dim3 gav(SS / 128, BB * HH);
    av_hmma_kernel<<<gav, 256, ADSM>>>(ph, pl, vth, vtl, ah, al);

    // out projection
    gemm_split_kernel<<<gg, 256, GDSM>>>(ah, al, woh, wol, bout, out, nullptr, nullptr, 0);
}